// round 15
// baseline (speedup 1.0000x reference)
#include <cuda_runtime.h>
#include <cuda_fp16.h>
#include <cstdint>
#include <cstddef>

// Problem constants
#define BB 8
#define NSEQ 4096
#define NN 32768            // BB*NSEQ nodes
#define H 128
#define EDGES 524288
#define RREL 8
#define NLAYERS 2
#define KC 1152             // concat K: 8 relations + self, each 128

#define PITCH_W 136         // fp16 elems per resident-W smem row (272B)
#define PITCH_A 40          // fp16 elems per 32-k chunk smem row (80B)

// ---- smem map for proj kernel (W resident, A streamed) ----
#define SW_H   0
#define SA_OFF (128 * PITCH_W)                 // 17408
#define SA_SZ  (128 * PITCH_A)                 // 5120 per buffer
#define SM_PROJ_ELEMS (SA_OFF + 2 * SA_SZ)     // 27648 fp16 = 55296 B

// ---- smem map for big GEMM (both streamed): A0 A1 W0 W1 ----
#define BG_A0 0
#define BG_A1 (128 * PITCH_A)
#define BG_W0 (2 * 128 * PITCH_A)
#define BG_W1 (3 * 128 * PITCH_A)
#define SM_BIG_BYTES (4 * 128 * PITCH_A * 2)   // 40960 B
#define NCHUNK (KC / 32)                       // 36

#define SCALE 64.0f
#define INV_SCALE2 (1.0f / 4096.0f)

// ---------------- scratch (static device globals; no allocation) ----------------
__device__ __half g_Cat[(size_t)NN * KC];        // [agg_0..agg_7, x_self] per node (72 MB)
__device__ __half g_Xf[(size_t)NN * H];          // node states, fp16 scaled x64 (8 MB)
__device__ __half g_Wp[(size_t)H * H];           // proj weights fp16 (x64)
__device__ __half g_Wcat[(size_t)NLAYERS * H * KC];  // concat weights fp16 (x64)
__device__ int g_degi[NN];                       // in-degree (int)
__device__ int g_off[NN];                        // CSR offsets
__device__ int g_slot[EDGES];                    // per-edge slot within its dst bucket
__device__ int g_epack[EDGES];                   // dst-bucketed packed edges: src | (r<<15)

// ---------------- helpers ----------------
__device__ __forceinline__ uint32_t smem_u32(const void* p) {
    uint32_t a;
    asm("{ .reg .u64 t; cvta.to.shared.u64 t, %1; cvt.u32.u64 %0, t; }" : "=r"(a) : "l"(p));
    return a;
}
__device__ __forceinline__ void cp_async16(uint32_t dst, const void* src) {
    asm volatile("cp.async.cg.shared.global [%0], [%1], 16;" :: "r"(dst), "l"(src));
}
__device__ __forceinline__ void cp_commit() {
    asm volatile("cp.async.commit_group;");
}
__device__ __forceinline__ void cp_wait0() {
    asm volatile("cp.async.wait_group 0;");
}
__device__ __forceinline__ void ldm_x4(uint32_t& r0, uint32_t& r1, uint32_t& r2, uint32_t& r3,
                                       uint32_t addr) {
    asm volatile("ldmatrix.sync.aligned.m8n8.x4.shared.b16 {%0,%1,%2,%3}, [%4];"
                 : "=r"(r0), "=r"(r1), "=r"(r2), "=r"(r3) : "r"(addr));
}
__device__ __forceinline__ void mma16816(float* d, const uint32_t* a, uint32_t b0, uint32_t b1) {
    asm volatile(
        "mma.sync.aligned.m16n8k16.row.col.f32.f16.f16.f32 "
        "{%0,%1,%2,%3}, {%4,%5,%6,%7}, {%8,%9}, {%0,%1,%2,%3};"
        : "+f"(d[0]), "+f"(d[1]), "+f"(d[2]), "+f"(d[3])
        : "r"(a[0]), "r"(a[1]), "r"(a[2]), "r"(a[3]), "r"(b0), "r"(b1));
}

// ---------------- embed: Xf = fp16(64*(concept_emb[cid]+kind_emb[kid])); zero degi -----
__global__ __launch_bounds__(256) void embed_kernel(const int* __restrict__ cid,
                                                    const int* __restrict__ kid,
                                                    const float* __restrict__ cemb,
                                                    const float* __restrict__ kemb) {
    int t = blockIdx.x * 256 + threadIdx.x;        // one float4 per thread
    if (t < NN) g_degi[t] = 0;
    int node = t >> 5;
    int q = t & 31;
    int c = __ldg(cid + node);
    int k = __ldg(kid + node);
    float4 a = __ldg(((const float4*)(cemb + (size_t)c * H)) + q);
    float4 b = __ldg(((const float4*)(kemb + (size_t)k * H)) + q);
    __half h[4];
    h[0] = __float2half(SCALE * (a.x + b.x));
    h[1] = __float2half(SCALE * (a.y + b.y));
    h[2] = __float2half(SCALE * (a.z + b.z));
    h[3] = __float2half(SCALE * (a.w + b.w));
    ((uint2*)g_Xf)[t] = *(const uint2*)h;
}

// ---------------- degree (int) + slot assignment ----------------
__global__ __launch_bounds__(256) void deg_kernel(const int* __restrict__ eidx) {
    int e = blockIdx.x * 256 + threadIdx.x;
    if (e >= EDGES) return;
    int dst = __ldg(eidx + EDGES + e);
    g_slot[e] = atomicAdd(&g_degi[dst], 1);
}

// ---------------- single-CTA scan: off = exclusive prefix of degi ----------------
__global__ __launch_bounds__(1024) void scan_kernel() {
    __shared__ int s[1024];
    int tid = threadIdx.x;
    int base = tid * 32;
    int v[32];
    int sum = 0;
#pragma unroll
    for (int i = 0; i < 32; i++) { v[i] = g_degi[base + i]; sum += v[i]; }
    s[tid] = sum;
    __syncthreads();
    for (int off = 1; off < 1024; off <<= 1) {
        int t = (tid >= off) ? s[tid - off] : 0;
        __syncthreads();
        s[tid] += t;
        __syncthreads();
    }
    int run = s[tid] - sum;
#pragma unroll
    for (int i = 0; i < 32; i++) {
        g_off[base + i] = run;
        run += v[i];
    }
}

// ---------------- scatter (no atomics): epack[off[dst]+slot[e]] = src|(r<<15) ----------
__global__ __launch_bounds__(256) void scatter_kernel(const int* __restrict__ eidx,
                                                      const int* __restrict__ etype) {
    int e = blockIdx.x * 256 + threadIdx.x;
    if (e >= EDGES) return;
    int src = __ldg(eidx + e);
    int dst = __ldg(eidx + EDGES + e);
    int r = __ldg(etype + e);
    g_epack[__ldg(&g_off[dst]) + __ldg(&g_slot[e])] = src | (r << 15);
}

// ---------------- weight conversion: proj fp16 + concat Wcat fp16 ----------------
// Wcat[l][g][j]: j<1024 -> relW[l][j>>7][g][j&127]; j>=1024 -> selfW[l][g][j-1024]
__global__ __launch_bounds__(256) void convert_w_kernel(const float* __restrict__ projW,
                                                        const float* __restrict__ selfW,
                                                        const float* __restrict__ relW) {
    int t = blockIdx.x * 256 + threadIdx.x;
    int o8 = t * 8;
    const int PROJ = H * H;                      // 16384
    const int PERL = H * KC;                     // 147456
    if (o8 >= PROJ + NLAYERS * PERL) return;
    const float* src;
    __half* dst;
    if (o8 < PROJ) {
        src = projW + o8;
        dst = g_Wp + o8;
    } else {
        int g0 = o8 - PROJ;
        int l = g0 / PERL;
        int o = g0 % PERL;
        int g = o / KC;
        int j = o % KC;
        if (j < RREL * H) {
            int r = j >> 7;
            int k = j & 127;
            src = relW + ((size_t)l * RREL + r) * H * H + g * H + k;
        } else {
            src = selfW + (size_t)l * H * H + g * H + (j - RREL * H);
        }
        dst = g_Wcat + (size_t)l * PERL + o;
    }
    float4 a = *(const float4*)src;
    float4 b = *(const float4*)(src + 4);
    float v[8] = {a.x, a.y, a.z, a.w, b.x, b.y, b.z, b.w};
    __half hi[8];
#pragma unroll
    for (int i = 0; i < 8; i++) hi[i] = __float2half(SCALE * v[i]);
    *(uint4*)dst = *(const uint4*)hi;
}

// ---------------- proj GEMM (128x128x128, W resident, A streamed; R14-verified) ------
// Xf = fp16 x64 of (E0 @ projW^T + projb), in-place over Xf
__global__ __launch_bounds__(256, 2) void mma_proj_kernel(const float* __restrict__ projb) {
    extern __shared__ __half sm[];
    const uint32_t sbase = smem_u32(sm);
    const int tid = threadIdx.x;
    const int m0 = blockIdx.x * 128;
    const __half* Ag = g_Xf + (size_t)m0 * H;

    {
#pragma unroll
        for (int it = 0; it < 8; it++) {
            int i = tid + it * 256;
            int r = i >> 4;
            int c = i & 15;
            cp_async16(sbase + (SW_H + r * PITCH_W + c * 8) * 2, g_Wp + r * H + c * 8);
        }
#pragma unroll
        for (int it = 0; it < 2; it++) {
            int i = tid + it * 256;
            int r = i >> 2;
            int c = i & 3;
            cp_async16(sbase + (SA_OFF + r * PITCH_A + c * 8) * 2, Ag + r * H + c * 8);
        }
        cp_commit();
        cp_wait0();
    }
    __syncthreads();

    const int wid = tid >> 5;
    const int lane = tid & 31;
    const int wm = wid >> 2;
    const int wn = wid & 3;

    float acc[4][4][4];
#pragma unroll
    for (int i = 0; i < 4; i++)
#pragma unroll
        for (int j = 0; j < 4; j++)
#pragma unroll
            for (int k = 0; k < 4; k++) acc[i][j][k] = 0.0f;

    const uint32_t lrow = lane & 15;
    const uint32_t lhalf = lane >> 4;
    const uint32_t aWh = sbase + (SW_H + (wn * 32 + lrow) * PITCH_W + lhalf * 8) * 2;
    const uint32_t aA0 = sbase + (SA_OFF + (wm * 64 + lrow) * PITCH_A + lhalf * 8) * 2;

#pragma unroll
    for (int kc = 0; kc < 4; kc++) {
        if (kc < 3) {
            int b = (kc + 1) & 1;
#pragma unroll
            for (int it = 0; it < 2; it++) {
                int i = tid + it * 256;
                int r = i >> 2;
                int c = i & 3;
                cp_async16(sbase + (SA_OFF + b * SA_SZ + r * PITCH_A + c * 8) * 2,
                           Ag + r * H + (kc + 1) * 32 + c * 8);
            }
            cp_commit();
        }
        const uint32_t aA = aA0 + (kc & 1) * (SA_SZ * 2);
#pragma unroll
        for (int kstep = 0; kstep < 2; kstep++) {
            const int ks = kc * 2 + kstep;
            const uint32_t wkoff = ks * 32;
            const uint32_t akoff = kstep * 32;
            uint32_t bh[2][4];
#pragma unroll
            for (int bi = 0; bi < 2; bi++) {
                ldm_x4(bh[bi][0], bh[bi][1], bh[bi][2], bh[bi][3],
                       aWh + bi * (16 * PITCH_W * 2) + wkoff);
            }
#pragma unroll
            for (int mi = 0; mi < 4; mi++) {
                uint32_t a[4];
                ldm_x4(a[0], a[1], a[2], a[3], aA + mi * (16 * PITCH_A * 2) + akoff);
#pragma unroll
                for (int bi = 0; bi < 2; bi++) {
                    mma16816(acc[mi][2 * bi + 0], a, bh[bi][0], bh[bi][2]);
                    mma16816(acc[mi][2 * bi + 1], a, bh[bi][1], bh[bi][3]);
                }
            }
        }
        if (kc < 3) {
            cp_wait0();
            __syncthreads();
        }
    }

    const int gID = lane >> 2;
    const int tig = lane & 3;
#pragma unroll
    for (int mi = 0; mi < 4; mi++) {
#pragma unroll
        for (int nt = 0; nt < 4; nt++) {
            int col = wn * 32 + nt * 8 + tig * 2;
            float b0 = __ldg(projb + col);
            float b1 = __ldg(projb + col + 1);
#pragma unroll
            for (int half = 0; half < 2; half++) {
                int row = m0 + wm * 64 + mi * 16 + gID + half * 8;
                float v0 = acc[mi][nt][2 * half + 0] * INV_SCALE2 + b0;
                float v1 = acc[mi][nt][2 * half + 1] * INV_SCALE2 + b1;
                __half2 hv;
                hv.x = __float2half(SCALE * v0);
                hv.y = __float2half(SCALE * v1);
                *(__half2*)(g_Xf + (size_t)row * H + col) = hv;
            }
        }
    }
}

// ---------------- agg_cat: per-relation sums of x_src + self copy -> Cat ----------------
// Warp per dst: gather x_src rows from L2-resident Xf, accumulate per relation (fp32),
// scale by 1/deg, write Cat[dst][r*128..]; copy Xf[dst] into block 8.
__global__ __launch_bounds__(256) void agg_cat_kernel() {
    int w = (blockIdx.x * 256 + threadIdx.x) >> 5;
    int lane = threadIdx.x & 31;
    int off = __ldg(&g_off[w]);
    int n = __ldg(&g_degi[w]);
    float inv = 1.0f / fmaxf((float)n, 1.0f);
    float acc[8][4];
#pragma unroll
    for (int r = 0; r < 8; r++)
#pragma unroll
        for (int q = 0; q < 4; q++) acc[r][q] = 0.0f;

    for (int b = 0; b < n; b += 32) {
        int m = min(32, n - b);
        int pk = (b + lane < n) ? __ldg(g_epack + off + b + lane) : 0;
        int j = 0;
        for (; j + 4 <= m; j += 4) {
            uint2 u[4];
            int rr[4];
#pragma unroll
            for (int q = 0; q < 4; q++) {
                int p = __shfl_sync(0xffffffffu, pk, j + q);
                rr[q] = (p >> 15) & 7;
                u[q] = __ldg(((const uint2*)(g_Xf + (size_t)(p & 0x7FFF) * H)) + lane);
            }
#pragma unroll
            for (int q = 0; q < 4; q++) {
                __half2 h0 = *(__half2*)&u[q].x;
                __half2 h1 = *(__half2*)&u[q].y;
                float2 f0 = __half22float2(h0);
                float2 f1 = __half22float2(h1);
                float* a = acc[rr[q]];
                a[0] += f0.x; a[1] += f0.y; a[2] += f1.x; a[3] += f1.y;
            }
        }
        for (; j < m; j++) {
            int p = __shfl_sync(0xffffffffu, pk, j);
            uint2 u = __ldg(((const uint2*)(g_Xf + (size_t)(p & 0x7FFF) * H)) + lane);
            __half2 h0 = *(__half2*)&u.x;
            __half2 h1 = *(__half2*)&u.y;
            float2 f0 = __half22float2(h0);
            float2 f1 = __half22float2(h1);
            float* a = acc[(p >> 15) & 7];
            a[0] += f0.x; a[1] += f0.y; a[2] += f1.x; a[3] += f1.y;
        }
    }

    __half* crow = g_Cat + (size_t)w * KC;
#pragma unroll
    for (int r = 0; r < 8; r++) {
        __half h[4];
        h[0] = __float2half(acc[r][0] * inv);
        h[1] = __float2half(acc[r][1] * inv);
        h[2] = __float2half(acc[r][2] * inv);
        h[3] = __float2half(acc[r][3] * inv);
        *(uint2*)(crow + r * H + lane * 4) = *(const uint2*)h;
    }
    // self block (block 8): raw copy of Xf row (already x64)
    uint2 x = ((const uint2*)(g_Xf + (size_t)w * H))[lane];
    *(uint2*)(crow + RREL * H + lane * 4) = x;
}

// ---------------- big GEMM: relu(Cat @ Wcat^T + selfb), K=1152, both streamed ----------
// layer 0 -> Xf fp16 x64; layer 1 -> out fp32 * mask.
__global__ __launch_bounds__(256, 2) void mma_big_kernel(const float* __restrict__ selfb,
                                                         int layer, float* __restrict__ out,
                                                         const int* __restrict__ mask) {
    extern __shared__ __half sm[];
    const uint32_t sbase = smem_u32(sm);
    const int tid = threadIdx.x;
    const int m0 = blockIdx.x * 128;
    const __half* Ag = g_Cat + (size_t)m0 * KC;
    const __half* Wg = g_Wcat + (size_t)layer * H * KC;

    // prologue: chunk 0 of A and W into buf 0 (each 128 rows x 4 uint4/row = 512)
    {
#pragma unroll
        for (int it = 0; it < 2; it++) {
            int i = tid + it * 256;
            int r = i >> 2;
            int c = i & 3;
            cp_async16(sbase + (BG_A0 + r * PITCH_A + c * 8) * 2, Ag + (size_t)r * KC + c * 8);
            cp_async16(sbase + (BG_W0 + r * PITCH_A + c * 8) * 2, Wg + (size_t)r * KC + c * 8);
        }
        cp_commit();
        cp_wait0();
    }
    __syncthreads();

    const int wid = tid >> 5;
    const int lane = tid & 31;
    const int wm = wid >> 2;
    const int wn = wid & 3;

    float acc[4][4][4];
#pragma unroll
    for (int i = 0; i < 4; i++)
#pragma unroll
        for (int j = 0; j < 4; j++)
#pragma unroll
            for (int k = 0; k < 4; k++) acc[i][j][k] = 0.0f;

    const uint32_t lrow = lane & 15;
    const uint32_t lhalf = lane >> 4;
    const uint32_t aAb[2] = {
        sbase + (BG_A0 + (wm * 64 + lrow) * PITCH_A + lhalf * 8) * 2,
        sbase + (BG_A1 + (wm * 64 + lrow) * PITCH_A + lhalf * 8) * 2};
    const uint32_t aWb[2] = {
        sbase + (BG_W0 + (wn * 32 + lrow) * PITCH_A + lhalf * 8) * 2,
        sbase + (BG_W1 + (wn * 32 + lrow) * PITCH_A + lhalf * 8) * 2};

#pragma unroll 2
    for (int kc = 0; kc < NCHUNK; kc++) {
        if (kc < NCHUNK - 1) {
            int b = (kc + 1) & 1;
            const uint32_t adst = sbase + (b ? BG_A1 : BG_A0) * 2;
            const uint32_t wdst = sbase + (b ? BG_W1 : BG_W0) * 2;
            int koffg = (kc + 1) * 32;
#pragma unroll
            for (int it = 0; it < 2; it++) {
                int i = tid + it * 256;
                int r = i >> 2;
                int c = i & 3;
                cp_async16(adst + (r * PITCH_A + c * 8) * 2, Ag + (size_t)r * KC + koffg + c * 8);
                cp_async16(wdst + (r * PITCH_A + c * 8) * 2, Wg + (size_t)r * KC + koffg + c * 8);
            }
            cp_commit();
        }

        const uint32_t aA = aAb[kc & 1];
        const uint32_t aW = aWb[kc & 1];
#pragma unroll
        for (int kstep = 0; kstep < 2; kstep++) {
            const uint32_t koff = kstep * 32;
            uint32_t bh[2][4];
#pragma unroll
            for (int bi = 0; bi < 2; bi++) {
                ldm_x4(bh[bi][0], bh[bi][1], bh[bi][2], bh[bi][3],
                       aW + bi * (16 * PITCH_A * 2) + koff);
            }
#pragma unroll
            for (int mi = 0; mi < 4; mi++) {
                uint32_t a[4];
                ldm_x4(a[0], a[1], a[2], a[3], aA + mi * (16 * PITCH_A * 2) + koff);
#pragma unroll
                for (int bi = 0; bi < 2; bi++) {
                    mma16816(acc[mi][2 * bi + 0], a, bh[bi][0], bh[bi][2]);
                    mma16816(acc[mi][2 * bi + 1], a, bh[bi][1], bh[bi][3]);
                }
            }
        }

        if (kc < NCHUNK - 1) {
            cp_wait0();
            __syncthreads();
        }
    }

    // epilogue: /4096 + bias, relu, output
    const int gID = lane >> 2;
    const int tig = lane & 3;
#pragma unroll
    for (int mi = 0; mi < 4; mi++) {
#pragma unroll
        for (int nt = 0; nt < 4; nt++) {
            int col = wn * 32 + nt * 8 + tig * 2;
            float b0 = __ldg(selfb + col);
            float b1 = __ldg(selfb + col + 1);
#pragma unroll
            for (int half = 0; half < 2; half++) {
                int row = m0 + wm * 64 + mi * 16 + gID + half * 8;
                float v0 = fmaxf(acc[mi][nt][2 * half + 0] * INV_SCALE2 + b0, 0.0f);
                float v1 = fmaxf(acc[mi][nt][2 * half + 1] * INV_SCALE2 + b1, 0.0f);
                if (layer == 0) {
                    __half2 hv;
                    hv.x = __float2half(SCALE * v0);
                    hv.y = __float2half(SCALE * v1);
                    *(__half2*)(g_Xf + (size_t)row * H + col) = hv;
                } else {
                    float mk = (float)__ldg(mask + row);
                    float2 fv = make_float2(v0 * mk, v1 * mk);
                    *(float2*)(out + (size_t)row * H + col) = fv;
                }
            }
        }
    }
}

// ---------------- launch ----------------
extern "C" void kernel_launch(void* const* d_in, const int* in_sizes, int n_in,
                              void* d_out, int out_size) {
    const int* cid     = (const int*)d_in[0];
    const int* kid     = (const int*)d_in[1];
    const int* mask    = (const int*)d_in[2];
    const int* eidx    = (const int*)d_in[3];
    const int* etype   = (const int*)d_in[4];
    const float* cemb  = (const float*)d_in[5];
    const float* kemb  = (const float*)d_in[6];
    const float* projW = (const float*)d_in[7];
    const float* projb = (const float*)d_in[8];
    const float* selfW = (const float*)d_in[9];
    const float* selfb = (const float*)d_in[10];
    const float* relW  = (const float*)d_in[11];
    float* out = (float*)d_out;

    const int proj_smem = SM_PROJ_ELEMS * 2;   // 55296
    cudaFuncSetAttribute(mma_proj_kernel, cudaFuncAttributeMaxDynamicSharedMemorySize, proj_smem);
    cudaFuncSetAttribute(mma_big_kernel, cudaFuncAttributeMaxDynamicSharedMemorySize, SM_BIG_BYTES);

    embed_kernel<<<(NN * 32) / 256, 256>>>(cid, kid, cemb, kemb);   // also zeroes degi
    deg_kernel<<<EDGES / 256, 256>>>(eidx);                         // counts + slots
    scan_kernel<<<1, 1024>>>();
    scatter_kernel<<<EDGES / 256, 256>>>(eidx, etype);              // no atomics
    {
        const int total8 = (H * H + NLAYERS * H * KC) / 8;
        convert_w_kernel<<<(total8 + 255) / 256, 256>>>(projW, selfW, relW);
    }
    mma_proj_kernel<<<NN / 128, 256, proj_smem>>>(projb);

    for (int l = 0; l < NLAYERS; l++) {
        agg_cat_kernel<<<(NN * 32) / 256, 256>>>();
        mma_big_kernel<<<NN / 128, 256, SM_BIG_BYTES>>>(selfb + l * H, l, out, mask);
    }
}

// round 16
// speedup vs baseline: 1.3330x; 1.3330x over previous
#include <cuda_runtime.h>
#include <cuda_fp16.h>
#include <cstdint>
#include <cstddef>

// Problem constants
#define BB 8
#define NSEQ 4096
#define NN 32768            // BB*NSEQ nodes
#define H 128
#define EDGES 524288
#define RREL 8
#define NLAYERS 2

#define PITCH_W 136         // fp16 elems per W smem row (272B)
#define PITCH_A 40          // fp16 elems per A-chunk smem row (80B; 32 data + 8 pad)

// ---- smem map for streaming GEMM kernels (fp16 element offsets) ----
#define SW_H   0
#define SA_OFF (128 * PITCH_W)                 // 17408
#define SA_SZ  (128 * PITCH_A)                 // 5120 per buffer
#define SM_ELEMS (SA_OFF + 2 * SA_SZ)          // 27648 fp16 = 55296 B

#define NMAT (1 + NLAYERS * (RREL + 1))        // 19 weight matrices
#define SCALE 64.0f
#define INV_SCALE2 (1.0f / 4096.0f)

// ---------------- scratch (static device globals; no allocation) ----------------
__device__ float g_Z[(size_t)NN * H];            // self-GEMM out / agg base (16 MB)
__device__ __half g_Y[(size_t)RREL * NN * H];    // per-relation messages, fp16 (64 MB)
__device__ __half g_Xf[(size_t)NN * H];          // node states, fp16 scaled x64 (8 MB)
__device__ __half g_Wh[(size_t)NMAT * H * H];    // weights fp16 (x64)
__device__ int g_degi[NN];                       // in-degree (int)
__device__ int g_off[NN];                        // CSR offsets (exclusive prefix of degi)
__device__ int g_slot[EDGES];                    // per-edge slot within its dst bucket
__device__ int g_epack[EDGES];                   // dst-bucketed packed edges: src | (r<<15)

// ---------------- helpers ----------------
__device__ __forceinline__ uint32_t smem_u32(const void* p) {
    uint32_t a;
    asm("{ .reg .u64 t; cvta.to.shared.u64 t, %1; cvt.u32.u64 %0, t; }" : "=r"(a) : "l"(p));
    return a;
}
__device__ __forceinline__ void cp_async16(uint32_t dst, const void* src) {
    asm volatile("cp.async.cg.shared.global [%0], [%1], 16;" :: "r"(dst), "l"(src));
}
__device__ __forceinline__ void cp_commit() {
    asm volatile("cp.async.commit_group;");
}
__device__ __forceinline__ void cp_wait0() {
    asm volatile("cp.async.wait_group 0;");
}
__device__ __forceinline__ void ldm_x4(uint32_t& r0, uint32_t& r1, uint32_t& r2, uint32_t& r3,
                                       uint32_t addr) {
    asm volatile("ldmatrix.sync.aligned.m8n8.x4.shared.b16 {%0,%1,%2,%3}, [%4];"
                 : "=r"(r0), "=r"(r1), "=r"(r2), "=r"(r3) : "r"(addr));
}
__device__ __forceinline__ void mma16816(float* d, const uint32_t* a, uint32_t b0, uint32_t b1) {
    asm volatile(
        "mma.sync.aligned.m16n8k16.row.col.f32.f16.f16.f32 "
        "{%0,%1,%2,%3}, {%4,%5,%6,%7}, {%8,%9}, {%0,%1,%2,%3};"
        : "+f"(d[0]), "+f"(d[1]), "+f"(d[2]), "+f"(d[3])
        : "r"(a[0]), "r"(a[1]), "r"(a[2]), "r"(a[3]), "r"(b0), "r"(b1));
}

// ---------------- embed: Xf = fp16(64*(concept_emb[cid]+kind_emb[kid])); zero degi -----
__global__ __launch_bounds__(256) void embed_kernel(const int* __restrict__ cid,
                                                    const int* __restrict__ kid,
                                                    const float* __restrict__ cemb,
                                                    const float* __restrict__ kemb) {
    int t = blockIdx.x * 256 + threadIdx.x;        // one float4 per thread
    if (t < NN) g_degi[t] = 0;
    int node = t >> 5;
    int q = t & 31;
    int c = __ldg(cid + node);
    int k = __ldg(kid + node);
    float4 a = __ldg(((const float4*)(cemb + (size_t)c * H)) + q);
    float4 b = __ldg(((const float4*)(kemb + (size_t)k * H)) + q);
    __half h[4];
    h[0] = __float2half(SCALE * (a.x + b.x));
    h[1] = __float2half(SCALE * (a.y + b.y));
    h[2] = __float2half(SCALE * (a.z + b.z));
    h[3] = __float2half(SCALE * (a.w + b.w));
    ((uint2*)g_Xf)[t] = *(const uint2*)h;
}

// ---------------- degree (int) + slot assignment ----------------
__global__ __launch_bounds__(256) void deg_kernel(const int* __restrict__ eidx) {
    int e = blockIdx.x * 256 + threadIdx.x;
    if (e >= EDGES) return;
    int dst = __ldg(eidx + EDGES + e);
    g_slot[e] = atomicAdd(&g_degi[dst], 1);
}

// ---------------- single-CTA scan: off = exclusive prefix of degi ----------------
__global__ __launch_bounds__(1024) void scan_kernel() {
    __shared__ int s[1024];
    int tid = threadIdx.x;
    int base = tid * 32;
    int v[32];
    int sum = 0;
#pragma unroll
    for (int i = 0; i < 32; i++) { v[i] = g_degi[base + i]; sum += v[i]; }
    s[tid] = sum;
    __syncthreads();
    for (int off = 1; off < 1024; off <<= 1) {
        int t = (tid >= off) ? s[tid - off] : 0;
        __syncthreads();
        s[tid] += t;
        __syncthreads();
    }
    int run = s[tid] - sum;   // exclusive prefix of this thread's chunk
#pragma unroll
    for (int i = 0; i < 32; i++) {
        g_off[base + i] = run;
        run += v[i];
    }
}

// ---------------- scatter (no atomics): epack[off[dst]+slot[e]] = src|(r<<15) ----------
__global__ __launch_bounds__(256) void scatter_kernel(const int* __restrict__ eidx,
                                                      const int* __restrict__ etype) {
    int e = blockIdx.x * 256 + threadIdx.x;
    if (e >= EDGES) return;
    int src = __ldg(eidx + e);
    int dst = __ldg(eidx + EDGES + e);
    int r = __ldg(etype + e);
    g_epack[__ldg(&g_off[dst]) + __ldg(&g_slot[e])] = src | (r << 15);
}

// ---------------- all-weight fp16 conversion (proj + both layers, one launch) --------
// layout: [proj][L0: rel0..7, self][L1: rel0..7, self], each 16384 elems
__global__ __launch_bounds__(256) void convert_w_all_kernel(const float* __restrict__ projW,
                                                            const float* __restrict__ selfW,
                                                            const float* __restrict__ relW) {
    int t = blockIdx.x * 256 + threadIdx.x;
    int f8 = t * 8;
    if (f8 >= NMAT * H * H) return;
    const float* src;
    if (f8 < H * H) {
        src = projW + f8;
    } else {
        int g = f8 - H * H;
        int l = g / ((RREL + 1) * H * H);
        int r = g % ((RREL + 1) * H * H);
        if (r < RREL * H * H) src = relW + (size_t)l * RREL * H * H + r;
        else src = selfW + (size_t)l * H * H + (r - RREL * H * H);
    }
    float4 a = *(const float4*)src;
    float4 b = *(const float4*)(src + 4);
    float v[8] = {a.x, a.y, a.z, a.w, b.x, b.y, b.z, b.w};
    __half hi[8];
#pragma unroll
    for (int i = 0; i < 8; i++) hi[i] = __float2half(SCALE * v[i]);
    ((uint4*)g_Wh)[t] = *(const uint4*)hi;
}

// ---------------- 128x128x128 fp16 HMMA tile GEMM (1-chain, streaming A) ----------------
// O[m][g] = sum_k A[m][k]*W[g][k] (scaled ops; /4096 + bias in epilogue).
// W (fp16) resident in smem; A streamed in 4 k-chunks of 32 with cp.async double buffer.
// OUT_MODE 0: fp32 -> O (+bias).  OUT_MODE 1: fp16 x64 -> Oh (+bias).  OUT_MODE 2: fp16 raw.
template <int OUT_MODE>
__device__ __forceinline__ void tile_gemm(const __half* __restrict__ A_g,
                                          const __half* __restrict__ Wh_g,
                                          const float* __restrict__ bias,
                                          float* __restrict__ O,
                                          __half* __restrict__ Oh, int m0) {
    extern __shared__ __half sm[];
    const uint32_t sbase = smem_u32(sm);
    const int tid = threadIdx.x;
    const __half* Ag = A_g + (size_t)m0 * H;

    {
#pragma unroll
        for (int it = 0; it < 8; it++) {
            int i = tid + it * 256;           // 0..2047 uint4 chunks (16 per row)
            int r = i >> 4;
            int c = i & 15;
            uint32_t dst = sbase + (SW_H + r * PITCH_W + c * 8) * 2;
            cp_async16(dst, Wh_g + r * H + c * 8);
        }
#pragma unroll
        for (int it = 0; it < 2; it++) {
            int i = tid + it * 256;           // 0..511
            int r = i >> 2;
            int c = i & 3;
            uint32_t dst = sbase + (SA_OFF + r * PITCH_A + c * 8) * 2;
            cp_async16(dst, Ag + r * H + c * 8);
        }
        cp_commit();
        cp_wait0();
    }
    __syncthreads();

    const int wid = tid >> 5;
    const int lane = tid & 31;
    const int wm = wid >> 2;
    const int wn = wid & 3;

    float acc[4][4][4];
#pragma unroll
    for (int i = 0; i < 4; i++)
#pragma unroll
        for (int j = 0; j < 4; j++)
#pragma unroll
            for (int k = 0; k < 4; k++) acc[i][j][k] = 0.0f;

    const uint32_t lrow = lane & 15;
    const uint32_t lhalf = lane >> 4;
    const uint32_t aWh = sbase + (SW_H + (wn * 32 + lrow) * PITCH_W + lhalf * 8) * 2;
    const uint32_t aA0 = sbase + (SA_OFF + (wm * 64 + lrow) * PITCH_A + lhalf * 8) * 2;

#pragma unroll
    for (int kc = 0; kc < 4; kc++) {
        if (kc < 3) {
            int b = (kc + 1) & 1;
#pragma unroll
            for (int it = 0; it < 2; it++) {
                int i = tid + it * 256;
                int r = i >> 2;
                int c = i & 3;
                uint32_t dst = sbase + (SA_OFF + b * SA_SZ + r * PITCH_A + c * 8) * 2;
                cp_async16(dst, Ag + r * H + (kc + 1) * 32 + c * 8);
            }
            cp_commit();
        }
        const uint32_t aA = aA0 + (kc & 1) * (SA_SZ * 2);
#pragma unroll
        for (int kstep = 0; kstep < 2; kstep++) {
            const int ks = kc * 2 + kstep;
            const uint32_t wkoff = ks * 32;
            const uint32_t akoff = kstep * 32;
            uint32_t bh[2][4];
#pragma unroll
            for (int bi = 0; bi < 2; bi++) {
                ldm_x4(bh[bi][0], bh[bi][1], bh[bi][2], bh[bi][3],
                       aWh + bi * (16 * PITCH_W * 2) + wkoff);
            }
#pragma unroll
            for (int mi = 0; mi < 4; mi++) {
                uint32_t a[4];
                ldm_x4(a[0], a[1], a[2], a[3], aA + mi * (16 * PITCH_A * 2) + akoff);
#pragma unroll
                for (int bi = 0; bi < 2; bi++) {
                    mma16816(acc[mi][2 * bi + 0], a, bh[bi][0], bh[bi][2]);
                    mma16816(acc[mi][2 * bi + 1], a, bh[bi][1], bh[bi][3]);
                }
            }
        }
        if (kc < 3) {
            cp_wait0();
            __syncthreads();
        }
    }

    const int gID = lane >> 2;
    const int tig = lane & 3;
#pragma unroll
    for (int mi = 0; mi < 4; mi++) {
#pragma unroll
        for (int nt = 0; nt < 4; nt++) {
            int col = wn * 32 + nt * 8 + tig * 2;
            float b0 = 0.0f, b1 = 0.0f;
            if (OUT_MODE != 2 && bias) { b0 = __ldg(bias + col); b1 = __ldg(bias + col + 1); }
#pragma unroll
            for (int half = 0; half < 2; half++) {
                int row = m0 + wm * 64 + mi * 16 + gID + half * 8;
                float v0 = acc[mi][nt][2 * half + 0] * INV_SCALE2 + b0;
                float v1 = acc[mi][nt][2 * half + 1] * INV_SCALE2 + b1;
                if (OUT_MODE == 0) {
                    float2 fv = make_float2(v0, v1);
                    *(float2*)(O + (size_t)row * H + col) = fv;
                } else if (OUT_MODE == 1) {
                    __half2 hv;
                    hv.x = __float2half(SCALE * v0);
                    hv.y = __float2half(SCALE * v1);
                    *(__half2*)(Oh + (size_t)row * H + col) = hv;
                } else {
                    __half2 hv;
                    hv.x = __float2half(v0);
                    hv.y = __float2half(v1);
                    *(__half2*)(Oh + (size_t)row * H + col) = hv;
                }
            }
        }
    }
}

// proj: Xf = fp16 x64 of (E0 @ projW^T + projb), in-place over Xf
__global__ __launch_bounds__(256, 2) void mma_proj_kernel(const float* __restrict__ projb) {
    tile_gemm<1>(g_Xf, g_Wh, projb, nullptr, g_Xf, blockIdx.x * 128);
}

// grid.y = 9: m<8 -> Y[m] = X @ rel_W[m]^T (fp16 out) ; m==8 -> Z = X @ self_W^T + b (fp32)
__global__ __launch_bounds__(256, 2) void mma_layer_kernel(const float* __restrict__ selfb,
                                                           int l) {
    int m = blockIdx.y;
    size_t woff = (size_t)(1 + l * (RREL + 1) + m) * H * H;
    const __half* wh = g_Wh + woff;
    if (m < RREL) {
        tile_gemm<2>(g_Xf, wh, nullptr, nullptr, g_Y + (size_t)m * NN * H, blockIdx.x * 128);
    } else {
        tile_gemm<0>(g_Xf, wh, selfb, g_Z, nullptr, blockIdx.x * 128);
    }
}

// ---------------- CSR aggregation + fused relu epilogue ----------------
// Warp per dst node: gather its bucketed edges' Y rows, accumulate fp32, add Z row,
// relu, write Xf (layer 0) or masked out (layer 1). No atomics.
__global__ __launch_bounds__(256) void agg_fused_kernel(int layer, float* __restrict__ out,
                                                        const int* __restrict__ mask) {
    int w = (blockIdx.x * 256 + threadIdx.x) >> 5;   // dst node, grid covers exactly NN
    int lane = threadIdx.x & 31;
    int off = __ldg(&g_off[w]);
    int n = __ldg(&g_degi[w]);
    float inv = 1.0f / fmaxf((float)n, 1.0f);
    float4 acc = make_float4(0.0f, 0.0f, 0.0f, 0.0f);

    for (int b = 0; b < n; b += 32) {
        int m = min(32, n - b);
        int pk = (b + lane < n) ? __ldg(g_epack + off + b + lane) : 0;
        int j = 0;
        for (; j + 4 <= m; j += 4) {
            uint2 u[4];
#pragma unroll
            for (int q = 0; q < 4; q++) {
                int p = __shfl_sync(0xffffffffu, pk, j + q);
                const uint2* yrow = (const uint2*)(g_Y +
                    ((size_t)((p >> 15) & 7) * NN + (p & 0x7FFF)) * H);
                u[q] = __ldg(yrow + lane);
            }
#pragma unroll
            for (int q = 0; q < 4; q++) {
                __half2 h0 = *(__half2*)&u[q].x;
                __half2 h1 = *(__half2*)&u[q].y;
                float2 f0 = __half22float2(h0);
                float2 f1 = __half22float2(h1);
                acc.x += f0.x; acc.y += f0.y; acc.z += f1.x; acc.w += f1.y;
            }
        }
        for (; j < m; j++) {
            int p = __shfl_sync(0xffffffffu, pk, j);
            const uint2* yrow = (const uint2*)(g_Y +
                ((size_t)((p >> 15) & 7) * NN + (p & 0x7FFF)) * H);
            uint2 u = __ldg(yrow + lane);
            __half2 h0 = *(__half2*)&u.x;
            __half2 h1 = *(__half2*)&u.y;
            float2 f0 = __half22float2(h0);
            float2 f1 = __half22float2(h1);
            acc.x += f0.x; acc.y += f0.y; acc.z += f1.x; acc.w += f1.y;
        }
    }

    float4 z = *(((const float4*)(g_Z + (size_t)w * H)) + lane);
    float4 v;
    v.x = fmaxf(z.x + acc.x * inv, 0.0f);
    v.y = fmaxf(z.y + acc.y * inv, 0.0f);
    v.z = fmaxf(z.z + acc.z * inv, 0.0f);
    v.w = fmaxf(z.w + acc.w * inv, 0.0f);

    if (layer == 0) {
        __half h[4];
        h[0] = __float2half(SCALE * v.x);
        h[1] = __float2half(SCALE * v.y);
        h[2] = __float2half(SCALE * v.z);
        h[3] = __float2half(SCALE * v.w);
        ((uint2*)g_Xf)[w * 32 + lane] = *(const uint2*)h;
    } else {
        float mk = (float)__ldg(mask + w);
        v.x *= mk; v.y *= mk; v.z *= mk; v.w *= mk;
        ((float4*)out)[w * 32 + lane] = v;
    }
}

// ---------------- launch ----------------
extern "C" void kernel_launch(void* const* d_in, const int* in_sizes, int n_in,
                              void* d_out, int out_size) {
    const int* cid     = (const int*)d_in[0];
    const int* kid     = (const int*)d_in[1];
    const int* mask    = (const int*)d_in[2];
    const int* eidx    = (const int*)d_in[3];
    const int* etype   = (const int*)d_in[4];
    const float* cemb  = (const float*)d_in[5];
    const float* kemb  = (const float*)d_in[6];
    const float* projW = (const float*)d_in[7];
    const float* projb = (const float*)d_in[8];
    const float* selfW = (const float*)d_in[9];
    const float* selfb = (const float*)d_in[10];
    const float* relW  = (const float*)d_in[11];
    float* out = (float*)d_out;

    const int smem_bytes = SM_ELEMS * 2;   // 55296
    cudaFuncSetAttribute(mma_proj_kernel, cudaFuncAttributeMaxDynamicSharedMemorySize, smem_bytes);
    cudaFuncSetAttribute(mma_layer_kernel, cudaFuncAttributeMaxDynamicSharedMemorySize, smem_bytes);

    embed_kernel<<<(NN * 32) / 256, 256>>>(cid, kid, cemb, kemb);   // also zeroes degi
    deg_kernel<<<EDGES / 256, 256>>>(eidx);                         // counts + slots
    scan_kernel<<<1, 1024>>>();
    scatter_kernel<<<EDGES / 256, 256>>>(eidx, etype);              // no atomics
    convert_w_all_kernel<<<(NMAT * H * H / 8 + 255) / 256, 256>>>(projW, selfW, relW);
    mma_proj_kernel<<<NN / 128, 256, smem_bytes>>>(projb);

    for (int l = 0; l < NLAYERS; l++) {
        mma_layer_kernel<<<dim3(NN / 128, RREL + 1), 256, smem_bytes>>>(selfb + l * H, l);
        agg_fused_kernel<<<(NN * 32) / 256, 256>>>(l, out, mask);
    }
}

// round 17
// speedup vs baseline: 1.5651x; 1.1740x over previous
#include <cuda_runtime.h>
#include <cuda_fp16.h>
#include <cstdint>
#include <cstddef>

// Problem constants
#define BB 8
#define NSEQ 4096
#define NN 32768            // BB*NSEQ nodes
#define H 128
#define EDGES 524288
#define RREL 8
#define NLAYERS 2

#define PITCH_W 136         // fp16 elems per W smem row (272B)
#define PITCH_A 40          // fp16 elems per A-chunk smem row (80B; 32 data + 8 pad)

// ---- smem map for streaming GEMM kernels (fp16 element offsets) ----
#define SW_H   0
#define SA_OFF (128 * PITCH_W)                 // 17408
#define SA_SZ  (128 * PITCH_A)                 // 5120 per buffer
#define SM_ELEMS (SA_OFF + 2 * SA_SZ)          // 27648 fp16 = 55296 B

#define NMAT (1 + NLAYERS * (RREL + 1))        // 19 weight matrices
#define SCALE 64.0f
#define INV_SCALE2 (1.0f / 4096.0f)

// ---------------- scratch (static device globals; no allocation) ----------------
__device__ float g_Z[(size_t)NN * H];            // self-GEMM out / agg base (16 MB)
__device__ __half g_Y[(size_t)RREL * NN * H];    // per-relation messages, fp16 (64 MB)
__device__ __half g_Xf[(size_t)NN * H];          // node states, fp16 scaled x64 (8 MB)
__device__ __half g_Wh[(size_t)NMAT * H * H];    // weights fp16 (x64)
__device__ int g_degi[NN];                       // in-degree (int)
__device__ int g_off[NN];                        // CSR offsets (exclusive prefix of degi)
__device__ int g_slot[EDGES];                    // per-edge slot within its dst bucket
__device__ int g_epack[EDGES];                   // dst-bucketed packed edges: src | (r<<15)

// ---------------- helpers ----------------
__device__ __forceinline__ uint32_t smem_u32(const void* p) {
    uint32_t a;
    asm("{ .reg .u64 t; cvta.to.shared.u64 t, %1; cvt.u32.u64 %0, t; }" : "=r"(a) : "l"(p));
    return a;
}
__device__ __forceinline__ void cp_async16(uint32_t dst, const void* src) {
    asm volatile("cp.async.cg.shared.global [%0], [%1], 16;" :: "r"(dst), "l"(src));
}
__device__ __forceinline__ void cp_commit() {
    asm volatile("cp.async.commit_group;");
}
__device__ __forceinline__ void cp_wait0() {
    asm volatile("cp.async.wait_group 0;");
}
__device__ __forceinline__ void ldm_x4(uint32_t& r0, uint32_t& r1, uint32_t& r2, uint32_t& r3,
                                       uint32_t addr) {
    asm volatile("ldmatrix.sync.aligned.m8n8.x4.shared.b16 {%0,%1,%2,%3}, [%4];"
                 : "=r"(r0), "=r"(r1), "=r"(r2), "=r"(r3) : "r"(addr));
}
__device__ __forceinline__ void mma16816(float* d, const uint32_t* a, uint32_t b0, uint32_t b1) {
    asm volatile(
        "mma.sync.aligned.m16n8k16.row.col.f32.f16.f16.f32 "
        "{%0,%1,%2,%3}, {%4,%5,%6,%7}, {%8,%9}, {%0,%1,%2,%3};"
        : "+f"(d[0]), "+f"(d[1]), "+f"(d[2]), "+f"(d[3])
        : "r"(a[0]), "r"(a[1]), "r"(a[2]), "r"(a[3]), "r"(b0), "r"(b1));
}

// ---------------- embed: Xf = fp16(64*(concept_emb[cid]+kind_emb[kid])) ----------------
__global__ __launch_bounds__(256) void embed_kernel(const int* __restrict__ cid,
                                                    const int* __restrict__ kid,
                                                    const float* __restrict__ cemb,
                                                    const float* __restrict__ kemb) {
    int t = blockIdx.x * 256 + threadIdx.x;        // one float4 per thread
    int node = t >> 5;
    int q = t & 31;
    int c = __ldg(cid + node);
    int k = __ldg(kid + node);
    float4 a = __ldg(((const float4*)(cemb + (size_t)c * H)) + q);
    float4 b = __ldg(((const float4*)(kemb + (size_t)k * H)) + q);
    __half h[4];
    h[0] = __float2half(SCALE * (a.x + b.x));
    h[1] = __float2half(SCALE * (a.y + b.y));
    h[2] = __float2half(SCALE * (a.z + b.z));
    h[3] = __float2half(SCALE * (a.w + b.w));
    ((uint2*)g_Xf)[t] = *(const uint2*)h;
}

// ---------------- edge-chain kernels (run on forked stream) ----------------
__global__ __launch_bounds__(256) void zero_deg_kernel() {
    int i = blockIdx.x * 256 + threadIdx.x;
    if (i < NN) g_degi[i] = 0;
}

__global__ __launch_bounds__(256) void deg_kernel(const int* __restrict__ eidx) {
    int e = blockIdx.x * 256 + threadIdx.x;
    if (e >= EDGES) return;
    int dst = __ldg(eidx + EDGES + e);
    g_slot[e] = atomicAdd(&g_degi[dst], 1);
}

// single-CTA scan: off = exclusive prefix of degi
__global__ __launch_bounds__(1024) void scan_kernel() {
    __shared__ int s[1024];
    int tid = threadIdx.x;
    int base = tid * 32;
    int v[32];
    int sum = 0;
#pragma unroll
    for (int i = 0; i < 32; i++) { v[i] = g_degi[base + i]; sum += v[i]; }
    s[tid] = sum;
    __syncthreads();
    for (int off = 1; off < 1024; off <<= 1) {
        int t = (tid >= off) ? s[tid - off] : 0;
        __syncthreads();
        s[tid] += t;
        __syncthreads();
    }
    int run = s[tid] - sum;   // exclusive prefix of this thread's chunk
#pragma unroll
    for (int i = 0; i < 32; i++) {
        g_off[base + i] = run;
        run += v[i];
    }
}

// scatter (no atomics): epack[off[dst]+slot[e]] = src|(r<<15)
__global__ __launch_bounds__(256) void scatter_kernel(const int* __restrict__ eidx,
                                                      const int* __restrict__ etype) {
    int e = blockIdx.x * 256 + threadIdx.x;
    if (e >= EDGES) return;
    int src = __ldg(eidx + e);
    int dst = __ldg(eidx + EDGES + e);
    int r = __ldg(etype + e);
    g_epack[__ldg(&g_off[dst]) + __ldg(&g_slot[e])] = src | (r << 15);
}

// ---------------- all-weight fp16 conversion (proj + both layers, one launch) --------
// layout: [proj][L0: rel0..7, self][L1: rel0..7, self], each 16384 elems
__global__ __launch_bounds__(256) void convert_w_all_kernel(const float* __restrict__ projW,
                                                            const float* __restrict__ selfW,
                                                            const float* __restrict__ relW) {
    int t = blockIdx.x * 256 + threadIdx.x;
    int f8 = t * 8;
    if (f8 >= NMAT * H * H) return;
    const float* src;
    if (f8 < H * H) {
        src = projW + f8;
    } else {
        int g = f8 - H * H;
        int l = g / ((RREL + 1) * H * H);
        int r = g % ((RREL + 1) * H * H);
        if (r < RREL * H * H) src = relW + (size_t)l * RREL * H * H + r;
        else src = selfW + (size_t)l * H * H + (r - RREL * H * H);
    }
    float4 a = *(const float4*)src;
    float4 b = *(const float4*)(src + 4);
    float v[8] = {a.x, a.y, a.z, a.w, b.x, b.y, b.z, b.w};
    __half hi[8];
#pragma unroll
    for (int i = 0; i < 8; i++) hi[i] = __float2half(SCALE * v[i]);
    ((uint4*)g_Wh)[t] = *(const uint4*)hi;
}

// ---------------- 128x128x128 fp16 HMMA tile GEMM (1-chain, streaming A) ----------------
// O[m][g] = sum_k A[m][k]*W[g][k] (scaled ops; /4096 + bias in epilogue).
// W (fp16) resident in smem; A streamed in 4 k-chunks of 32 with cp.async double buffer.
// OUT_MODE 0: fp32 -> O (+bias).  OUT_MODE 1: fp16 x64 -> Oh (+bias).  OUT_MODE 2: fp16 raw.
template <int OUT_MODE>
__device__ __forceinline__ void tile_gemm(const __half* __restrict__ A_g,
                                          const __half* __restrict__ Wh_g,
                                          const float* __restrict__ bias,
                                          float* __restrict__ O,
                                          __half* __restrict__ Oh, int m0) {
    extern __shared__ __half sm[];
    const uint32_t sbase = smem_u32(sm);
    const int tid = threadIdx.x;
    const __half* Ag = A_g + (size_t)m0 * H;

    {
#pragma unroll
        for (int it = 0; it < 8; it++) {
            int i = tid + it * 256;           // 0..2047 uint4 chunks (16 per row)
            int r = i >> 4;
            int c = i & 15;
            uint32_t dst = sbase + (SW_H + r * PITCH_W + c * 8) * 2;
            cp_async16(dst, Wh_g + r * H + c * 8);
        }
#pragma unroll
        for (int it = 0; it < 2; it++) {
            int i = tid + it * 256;           // 0..511
            int r = i >> 2;
            int c = i & 3;
            uint32_t dst = sbase + (SA_OFF + r * PITCH_A + c * 8) * 2;
            cp_async16(dst, Ag + r * H + c * 8);
        }
        cp_commit();
        cp_wait0();
    }
    __syncthreads();

    const int wid = tid >> 5;
    const int lane = tid & 31;
    const int wm = wid >> 2;
    const int wn = wid & 3;

    float acc[4][4][4];
#pragma unroll
    for (int i = 0; i < 4; i++)
#pragma unroll
        for (int j = 0; j < 4; j++)
#pragma unroll
            for (int k = 0; k < 4; k++) acc[i][j][k] = 0.0f;

    const uint32_t lrow = lane & 15;
    const uint32_t lhalf = lane >> 4;
    const uint32_t aWh = sbase + (SW_H + (wn * 32 + lrow) * PITCH_W + lhalf * 8) * 2;
    const uint32_t aA0 = sbase + (SA_OFF + (wm * 64 + lrow) * PITCH_A + lhalf * 8) * 2;

#pragma unroll
    for (int kc = 0; kc < 4; kc++) {
        if (kc < 3) {
            int b = (kc + 1) & 1;
#pragma unroll
            for (int it = 0; it < 2; it++) {
                int i = tid + it * 256;
                int r = i >> 2;
                int c = i & 3;
                uint32_t dst = sbase + (SA_OFF + b * SA_SZ + r * PITCH_A + c * 8) * 2;
                cp_async16(dst, Ag + r * H + (kc + 1) * 32 + c * 8);
            }
            cp_commit();
        }
        const uint32_t aA = aA0 + (kc & 1) * (SA_SZ * 2);
#pragma unroll
        for (int kstep = 0; kstep < 2; kstep++) {
            const int ks = kc * 2 + kstep;
            const uint32_t wkoff = ks * 32;
            const uint32_t akoff = kstep * 32;
            uint32_t bh[2][4];
#pragma unroll
            for (int bi = 0; bi < 2; bi++) {
                ldm_x4(bh[bi][0], bh[bi][1], bh[bi][2], bh[bi][3],
                       aWh + bi * (16 * PITCH_W * 2) + wkoff);
            }
#pragma unroll
            for (int mi = 0; mi < 4; mi++) {
                uint32_t a[4];
                ldm_x4(a[0], a[1], a[2], a[3], aA + mi * (16 * PITCH_A * 2) + akoff);
#pragma unroll
                for (int bi = 0; bi < 2; bi++) {
                    mma16816(acc[mi][2 * bi + 0], a, bh[bi][0], bh[bi][2]);
                    mma16816(acc[mi][2 * bi + 1], a, bh[bi][1], bh[bi][3]);
                }
            }
        }
        if (kc < 3) {
            cp_wait0();
            __syncthreads();
        }
    }

    const int gID = lane >> 2;
    const int tig = lane & 3;
#pragma unroll
    for (int mi = 0; mi < 4; mi++) {
#pragma unroll
        for (int nt = 0; nt < 4; nt++) {
            int col = wn * 32 + nt * 8 + tig * 2;
            float b0 = 0.0f, b1 = 0.0f;
            if (OUT_MODE != 2 && bias) { b0 = __ldg(bias + col); b1 = __ldg(bias + col + 1); }
#pragma unroll
            for (int half = 0; half < 2; half++) {
                int row = m0 + wm * 64 + mi * 16 + gID + half * 8;
                float v0 = acc[mi][nt][2 * half + 0] * INV_SCALE2 + b0;
                float v1 = acc[mi][nt][2 * half + 1] * INV_SCALE2 + b1;
                if (OUT_MODE == 0) {
                    float2 fv = make_float2(v0, v1);
                    *(float2*)(O + (size_t)row * H + col) = fv;
                } else if (OUT_MODE == 1) {
                    __half2 hv;
                    hv.x = __float2half(SCALE * v0);
                    hv.y = __float2half(SCALE * v1);
                    *(__half2*)(Oh + (size_t)row * H + col) = hv;
                } else {
                    __half2 hv;
                    hv.x = __float2half(v0);
                    hv.y = __float2half(v1);
                    *(__half2*)(Oh + (size_t)row * H + col) = hv;
                }
            }
        }
    }
}

// proj: Xf = fp16 x64 of (E0 @ projW^T + projb), in-place over Xf
__global__ __launch_bounds__(256, 2) void mma_proj_kernel(const float* __restrict__ projb) {
    tile_gemm<1>(g_Xf, g_Wh, projb, nullptr, g_Xf, blockIdx.x * 128);
}

// grid.y = 9: m<8 -> Y[m] = X @ rel_W[m]^T (fp16 out) ; m==8 -> Z = X @ self_W^T + b (fp32)
__global__ __launch_bounds__(256, 2) void mma_layer_kernel(const float* __restrict__ selfb,
                                                           int l) {
    int m = blockIdx.y;
    size_t woff = (size_t)(1 + l * (RREL + 1) + m) * H * H;
    const __half* wh = g_Wh + woff;
    if (m < RREL) {
        tile_gemm<2>(g_Xf, wh, nullptr, nullptr, g_Y + (size_t)m * NN * H, blockIdx.x * 128);
    } else {
        tile_gemm<0>(g_Xf, wh, selfb, g_Z, nullptr, blockIdx.x * 128);
    }
}

// ---------------- CSR aggregation + fused relu epilogue ----------------
// Warp per dst node: gather its bucketed edges' Y rows, accumulate fp32, add Z row,
// relu, write Xf (layer 0) or masked out (layer 1). No atomics.
__global__ __launch_bounds__(256) void agg_fused_kernel(int layer, float* __restrict__ out,
                                                        const int* __restrict__ mask) {
    int w = (blockIdx.x * 256 + threadIdx.x) >> 5;   // dst node, grid covers exactly NN
    int lane = threadIdx.x & 31;
    int off = __ldg(&g_off[w]);
    int n = __ldg(&g_degi[w]);
    float inv = 1.0f / fmaxf((float)n, 1.0f);
    float4 acc = make_float4(0.0f, 0.0f, 0.0f, 0.0f);

    for (int b = 0; b < n; b += 32) {
        int m = min(32, n - b);
        int pk = (b + lane < n) ? __ldg(g_epack + off + b + lane) : 0;
        int j = 0;
        for (; j + 4 <= m; j += 4) {
            uint2 u[4];
#pragma unroll
            for (int q = 0; q < 4; q++) {
                int p = __shfl_sync(0xffffffffu, pk, j + q);
                const uint2* yrow = (const uint2*)(g_Y +
                    ((size_t)((p >> 15) & 7) * NN + (p & 0x7FFF)) * H);
                u[q] = __ldg(yrow + lane);
            }
#pragma unroll
            for (int q = 0; q < 4; q++) {
                __half2 h0 = *(__half2*)&u[q].x;
                __half2 h1 = *(__half2*)&u[q].y;
                float2 f0 = __half22float2(h0);
                float2 f1 = __half22float2(h1);
                acc.x += f0.x; acc.y += f0.y; acc.z += f1.x; acc.w += f1.y;
            }
        }
        for (; j < m; j++) {
            int p = __shfl_sync(0xffffffffu, pk, j);
            const uint2* yrow = (const uint2*)(g_Y +
                ((size_t)((p >> 15) & 7) * NN + (p & 0x7FFF)) * H);
            uint2 u = __ldg(yrow + lane);
            __half2 h0 = *(__half2*)&u.x;
            __half2 h1 = *(__half2*)&u.y;
            float2 f0 = __half22float2(h0);
            float2 f1 = __half22float2(h1);
            acc.x += f0.x; acc.y += f0.y; acc.z += f1.x; acc.w += f1.y;
        }
    }

    float4 z = *(((const float4*)(g_Z + (size_t)w * H)) + lane);
    float4 v;
    v.x = fmaxf(z.x + acc.x * inv, 0.0f);
    v.y = fmaxf(z.y + acc.y * inv, 0.0f);
    v.z = fmaxf(z.z + acc.z * inv, 0.0f);
    v.w = fmaxf(z.w + acc.w * inv, 0.0f);

    if (layer == 0) {
        __half h[4];
        h[0] = __float2half(SCALE * v.x);
        h[1] = __float2half(SCALE * v.y);
        h[2] = __float2half(SCALE * v.z);
        h[3] = __float2half(SCALE * v.w);
        ((uint2*)g_Xf)[w * 32 + lane] = *(const uint2*)h;
    } else {
        float mk = (float)__ldg(mask + w);
        v.x *= mk; v.y *= mk; v.z *= mk; v.w *= mk;
        ((float4*)out)[w * 32 + lane] = v;
    }
}

// ---------------- launch ----------------
extern "C" void kernel_launch(void* const* d_in, const int* in_sizes, int n_in,
                              void* d_out, int out_size) {
    const int* cid     = (const int*)d_in[0];
    const int* kid     = (const int*)d_in[1];
    const int* mask    = (const int*)d_in[2];
    const int* eidx    = (const int*)d_in[3];
    const int* etype   = (const int*)d_in[4];
    const float* cemb  = (const float*)d_in[5];
    const float* kemb  = (const float*)d_in[6];
    const float* projW = (const float*)d_in[7];
    const float* projb = (const float*)d_in[8];
    const float* selfW = (const float*)d_in[9];
    const float* selfb = (const float*)d_in[10];
    const float* relW  = (const float*)d_in[11];
    float* out = (float*)d_out;

    const int smem_bytes = SM_ELEMS * 2;   // 55296
    cudaFuncSetAttribute(mma_proj_kernel, cudaFuncAttributeMaxDynamicSharedMemorySize, smem_bytes);
    cudaFuncSetAttribute(mma_layer_kernel, cudaFuncAttributeMaxDynamicSharedMemorySize, smem_bytes);

    // One-time host objects (no device memory). The enqueued work is identical
    // on every call; these only let the captured graph carry a parallel branch.
    static cudaStream_t s2 = nullptr;
    static cudaEvent_t evFork = nullptr, evJoin = nullptr;
    if (!s2) {
        cudaStreamCreateWithFlags(&s2, cudaStreamNonBlocking);
        cudaEventCreateWithFlags(&evFork, cudaEventDisableTiming);
        cudaEventCreateWithFlags(&evJoin, cudaEventDisableTiming);
    }

    // fork edge-preprocessing chain onto s2 (independent of embed/proj/layer GEMMs)
    cudaEventRecord(evFork, 0);
    cudaStreamWaitEvent(s2, evFork, 0);
    zero_deg_kernel<<<NN / 256, 256, 0, s2>>>();
    deg_kernel<<<EDGES / 256, 256, 0, s2>>>(eidx);
    scan_kernel<<<1, 1024, 0, s2>>>();
    scatter_kernel<<<EDGES / 256, 256, 0, s2>>>(eidx, etype);
    cudaEventRecord(evJoin, s2);

    // main chain
    embed_kernel<<<(NN * 32) / 256, 256>>>(cid, kid, cemb, kemb);
    convert_w_all_kernel<<<(NMAT * H * H / 8 + 255) / 256, 256>>>(projW, selfW, relW);
    mma_proj_kernel<<<NN / 128, 256, smem_bytes>>>(projb);

    // L0 GEMMs don't need edge data; join before the first aggregation
    mma_layer_kernel<<<dim3(NN / 128, RREL + 1), 256, smem_bytes>>>(selfb, 0);
    cudaStreamWaitEvent(0, evJoin, 0);
    agg_fused_kernel<<<(NN * 32) / 256, 256>>>(0, out, mask);

    mma_layer_kernel<<<dim3(NN / 128, RREL + 1), 256, smem_bytes>>>(selfb + H, 1);
    agg_fused_kernel<<<(NN * 32) / 256, 256>>>(1, out, mask);
}